// round 7
// baseline (speedup 1.0000x reference)
#include <cuda_runtime.h>
#include <math_constants.h>

#define BN    8
#define BC    256
#define BNF   16
#define BWH   784            // 28*28
#define CSTR  (BNF*BWH)      // 12544 floats between channels
#define CSTR4 (CSTR/4)       // 3136 float4
#define NV4   (BWH/4)        // 196 float4 per (n,f) wh-row
#define NTHR  1024
#define NCG   8              // channel groups in phase 1
#define CPG   (BC/NCG)       // 32 channels per group
#define NDOT  24             // channels dotted via LDG per group
#define CACHE_PER_G 8        // channels copied to smem per group (c%32 in [24,32))
#define NCACHE (NCG*CACHE_PER_G)   // 64 cached channels
#define CPW   4              // channels per warp-pass in phase 3

// dynamic smem (floats): scache[64*784]=50176, part[8*784]=6272, sc[784]
#define SCACHE_F (NCACHE * BWH)
#define PART_F   (NCG * BWH)
#define DYN_F    (SCACHE_F + PART_F + BWH)
#define DYN_B    (DYN_F * 4)        // 228,928 B (opt-in; R6 proved it launches)

__global__ __launch_bounds__(NTHR, 1)
void mfla_kernel(const float* __restrict__ l,
                 const float* __restrict__ g,
                 const float* __restrict__ w,
                 float* __restrict__ outc,   // [N,NF,W,H]
                 float* __restrict__ outg)   // [N,C,NF]
{
    extern __shared__ __align__(16) float dyn[];
    float* scache = dyn;                     // [64][784]  cached channels
    float* part   = dyn + SCACHE_F;          // [8][784]   group partial dots
    float* sc     = part + PART_F;           // [784]      exp values

    __shared__ float sw[BC];
    __shared__ float swc[NCACHE];            // weights of cached channels, cache order
    __shared__ float red[32];
    __shared__ float s_gdot, s_inv;

    const int tid = threadIdx.x;
    const int n   = blockIdx.x >> 4;
    const int f   = blockIdx.x & 15;
    const float*  lb  = l + ((size_t)n * BC * BNF + f) * BWH;  // lb[c*CSTR + wh]
    const float4* lb4 = reinterpret_cast<const float4*>(lb);

    // ---- weights to smem + gdot = sum_c g[n,c]*w[c] ----
    float p = 0.f;
    if (tid < BC) {
        float wv = w[tid];
        sw[tid] = wv;
        p = g[n * BC + tid] * wv;
    }
    if (tid < NCACHE)   // cache row r -> channel (r/8)*32 + 24 + r%8
        swc[tid] = w[(tid >> 3) * CPG + NDOT + (tid & 7)];
    #pragma unroll
    for (int o = 16; o; o >>= 1) p += __shfl_xor_sync(0xffffffffu, p, o);
    if ((tid & 31) == 0) red[tid >> 5] = p;
    __syncthreads();
    if (tid < 32) {
        float v = red[tid];
        #pragma unroll
        for (int o = 16; o; o >>= 1) v += __shfl_xor_sync(0xffffffffu, v, o);
        if (tid == 0) s_gdot = v;
    }
    __syncthreads();

    // ---- Phase 1: dot 24 channels (LDG.128, no STS coupling) + pure copy of 8 ----
    {
        const int cg = tid >> 7;       // 0..7
        const int wl = tid & 127;      // 0..127
        const int c0 = cg * CPG;
        float4* pv = reinterpret_cast<float4*>(part + cg * BWH);
        float4* cv = reinterpret_cast<float4*>(scache) + (size_t)cg * CACHE_PER_G * NV4;
        for (int i = wl; i < NV4; i += 128) {
            const float4* lp = lb4 + (size_t)c0 * CSTR4 + i;
            // (a) dot over first 24 channels — identical shape to R4's loop
            float4 a = make_float4(0.f, 0.f, 0.f, 0.f);
            #pragma unroll
            for (int c = 0; c < NDOT; ++c) {
                float4 v = lp[(size_t)c * CSTR4];
                float  wv = sw[c0 + c];
                a.x = fmaf(v.x, wv, a.x);
                a.y = fmaf(v.y, wv, a.y);
                a.z = fmaf(v.z, wv, a.z);
                a.w = fmaf(v.w, wv, a.w);
            }
            pv[i] = a;
            // (b) pure copy of channels 24..31 — independent loads, batched STS
            float4 t[CACHE_PER_G];
            #pragma unroll
            for (int k = 0; k < CACHE_PER_G; ++k)
                t[k] = lp[(size_t)(NDOT + k) * CSTR4];
            #pragma unroll
            for (int k = 0; k < CACHE_PER_G; ++k)
                cv[(size_t)k * NV4 + i] = t[k];
        }
    }
    __syncthreads();

    // ---- Phase 1b: combine group partials + cached-channel dot (smem) + exp ----
    float se = 0.f;
    if (tid < BWH) {
        float v = s_gdot;
        #pragma unroll
        for (int k = 0; k < NCG; ++k) v += part[k * BWH + tid];
        #pragma unroll
        for (int r = 0; r < NCACHE; ++r)       // conflict-free: stride-1 over tid
            v = fmaf(scache[r * BWH + tid], swc[r], v);
        outc[((size_t)n * BNF + f) * BWH + tid] = v;
        float e = __expf(v);
        sc[tid] = e;
        se = e;
    }
    // ---- Phase 2: block-reduce exp-sum ----
    #pragma unroll
    for (int o = 16; o; o >>= 1) se += __shfl_xor_sync(0xffffffffu, se, o);
    if ((tid & 31) == 0) red[tid >> 5] = se;
    __syncthreads();
    if (tid < 32) {
        float v = red[tid];
        #pragma unroll
        for (int o = 16; o; o >>= 1) v += __shfl_xor_sync(0xffffffffu, v, o);
        if (tid == 0) s_inv = 1.0f / v;
    }
    __syncthreads();

    // ---- Phase 3: g_out, 4 ch/warp-pass; c%32 in [24,32) served from smem ----
    {
        const int warp = tid >> 5;
        const int lane = tid & 31;
        const float inv = s_inv;
        const float4* av  = reinterpret_cast<const float4*>(sc);
        const float4* scv = reinterpret_cast<const float4*>(scache);
        #pragma unroll
        for (int blk = 0; blk < BC / (32 * CPW); ++blk) {   // 2 passes
            const int c0 = blk * 32 * CPW + warp * CPW;
            float acc[CPW] = {0.f, 0.f, 0.f, 0.f};
            if ((c0 & 31) >= NDOT) {
                const float4* sv = scv +
                    (size_t)((c0 >> 5) * CACHE_PER_G + (c0 & 31) - NDOT) * NV4;
                for (int i = lane; i < NV4; i += 32) {
                    float4 a4 = av[i];
                    #pragma unroll
                    for (int k = 0; k < CPW; ++k) {
                        float4 l4 = sv[(size_t)k * NV4 + i];
                        acc[k] += a4.x * l4.x + a4.y * l4.y + a4.z * l4.z + a4.w * l4.w;
                    }
                }
            } else {
                const float4* lv = lb4 + (size_t)c0 * CSTR4;
                for (int i = lane; i < NV4; i += 32) {
                    float4 a4 = av[i];
                    #pragma unroll
                    for (int k = 0; k < CPW; ++k) {
                        float4 l4 = lv[(size_t)k * CSTR4 + i];
                        acc[k] += a4.x * l4.x + a4.y * l4.y + a4.z * l4.z + a4.w * l4.w;
                    }
                }
            }
            #pragma unroll
            for (int k = 0; k < CPW; ++k) {
                float a = acc[k];
                #pragma unroll
                for (int o = 16; o; o >>= 1) a += __shfl_xor_sync(0xffffffffu, a, o);
                if (lane == 0)
                    outg[((size_t)n * BC + c0 + k) * BNF + f] = a * inv;
            }
        }
    }
}

extern "C" void kernel_launch(void* const* d_in, const int* in_sizes, int n_in,
                              void* d_out, int out_size)
{
    const float* l = (const float*)d_in[0];
    const float* g = (const float*)d_in[1];
    const float* w = (const float*)d_in[2];
    float* out  = (float*)d_out;
    float* outc = out;                              // 8*16*28*28 = 100352 floats
    float* outg = out + (size_t)BN * BNF * BWH;     // 8*256*16   = 32768 floats

    cudaFuncSetAttribute(mfla_kernel,
                         cudaFuncAttributeMaxDynamicSharedMemorySize, DYN_B);
    mfla_kernel<<<BN * BNF, NTHR, DYN_B>>>(l, g, w, outc, outg);
}

// round 8
// speedup vs baseline: 1.0860x; 1.0860x over previous
#include <cuda_runtime.h>
#include <math_constants.h>
#include <cstdint>

#define BN    8
#define BC    256
#define BNF   16
#define BWH   784            // 28*28
#define CSTR  (BNF*BWH)      // 12544 floats between channels
#define CSTR4 (CSTR/4)       // 3136 float4
#define NV4   (BWH/4)        // 196 float4 per wh-row
#define NTHR  512
#define CPCTA 128            // channels per CTA (cluster of 2 covers 256)
#define NCG   4              // phase-1 groups per CTA
#define CPG   32             // channels per group
#define CPW   4              // channels per warp-pass in phase 3

__global__ __launch_bounds__(NTHR, 2) __cluster_dims__(2, 1, 1)
void mfla_kernel(const float* __restrict__ l,
                 const float* __restrict__ g,
                 const float* __restrict__ w,
                 float* __restrict__ outc,   // [N,NF,W,H]
                 float* __restrict__ outg)   // [N,C,NF]
{
    __shared__ float sw[BC];
    __shared__ __align__(16) float part[NCG * BWH];   // 4 x 784 group partials
    __shared__ __align__(16) float cpart[BWH];        // this CTA's 128-ch partial c
    __shared__ __align__(16) float sc[BWH];           // exp values (full c)
    __shared__ float red[16];
    __shared__ float s_gdot, s_inv;

    const int tid = threadIdx.x;
    uint32_t rank;
    asm("mov.u32 %0, %%cluster_ctarank;" : "=r"(rank));
    const int cl = blockIdx.x >> 1;          // cluster id = n*16 + f
    const int n  = cl >> 4;
    const int f  = cl & 15;
    const int cbase = (int)rank * CPCTA;     // my channel range [cbase, cbase+128)

    const float*  lb  = l + ((size_t)(n * BC + cbase) * BNF + f) * BWH; // lb[c*CSTR+wh]
    const float4* lb4 = reinterpret_cast<const float4*>(lb);

    // ---- weights to smem + gdot = sum over ALL 256 channels (redundant/CTA) ----
    float p = 0.f;
    if (tid < BC) {
        float wv = w[tid];
        sw[tid] = wv;
        p = g[n * BC + tid] * wv;
    }
    #pragma unroll
    for (int o = 16; o; o >>= 1) p += __shfl_xor_sync(0xffffffffu, p, o);
    if ((tid & 31) == 0) red[tid >> 5] = p;
    __syncthreads();
    if (tid < 16) {
        float v = red[tid];
        #pragma unroll
        for (int o = 8; o; o >>= 1) v += __shfl_xor_sync(0xffffu, v, o);
        if (tid == 0) s_gdot = v;
    }
    __syncthreads();

    // ---- Phase 1: my 128 channels, 4 groups x 128 wh4-lanes, LDG.128 (R4 shape) ----
    {
        const int cg = tid >> 7;       // 0..3
        const int wl = tid & 127;      // 0..127
        const int c0 = cg * CPG;       // local channel base within my 128
        float4* pv = reinterpret_cast<float4*>(part + cg * BWH);
        for (int i = wl; i < NV4; i += 128) {
            const float4* lp = lb4 + (size_t)c0 * CSTR4 + i;
            float4 a = make_float4(0.f, 0.f, 0.f, 0.f);
            #pragma unroll
            for (int c = 0; c < CPG; ++c) {
                float4 v = lp[(size_t)c * CSTR4];
                float  wv = sw[cbase + c0 + c];
                a.x = fmaf(v.x, wv, a.x);
                a.y = fmaf(v.y, wv, a.y);
                a.z = fmaf(v.z, wv, a.z);
                a.w = fmaf(v.w, wv, a.w);
            }
            pv[i] = a;
        }
    }
    __syncthreads();

    // ---- Phase 1b: combine my 4 group partials -> cpart ----
    for (int wh = tid; wh < BWH; wh += NTHR) {
        float v = part[wh] + part[BWH + wh] + part[2 * BWH + wh] + part[3 * BWH + wh];
        cpart[wh] = v;
    }
    __syncthreads();
    // make cpart visible cluster-wide, and see peer's
    asm volatile("barrier.cluster.arrive.aligned;" ::: "memory");
    asm volatile("barrier.cluster.wait.aligned;"   ::: "memory");

    // ---- Phase 1c: c = mine + peer (DSMEM) + gdot; rank0 writes c; exp; sum ----
    float se = 0.f;
    {
        const uint32_t caddr = (uint32_t)__cvta_generic_to_shared(cpart);
        const uint32_t peer  = rank ^ 1u;
        const float gd = s_gdot;
        float* cout = outc + ((size_t)n * BNF + f) * BWH;
        for (int wh = tid; wh < BWH; wh += NTHR) {
            uint32_t ra;
            asm("mapa.shared::cluster.u32 %0, %1, %2;" : "=r"(ra) : "r"(caddr + 4u * wh), "r"(peer));
            float pv;
            asm volatile("ld.shared::cluster.f32 %0, [%1];" : "=f"(pv) : "r"(ra));
            float v = cpart[wh] + pv + gd;
            if (rank == 0) cout[wh] = v;
            float e = __expf(v);
            sc[wh] = e;
            se += e;
        }
    }
    // ---- Phase 2: block-reduce exp-sum (softmax denominator) ----
    #pragma unroll
    for (int o = 16; o; o >>= 1) se += __shfl_xor_sync(0xffffffffu, se, o);
    if ((tid & 31) == 0) red[tid >> 5] = se;
    __syncthreads();
    if (tid < 16) {
        float v = red[tid];
        #pragma unroll
        for (int o = 8; o; o >>= 1) v += __shfl_xor_sync(0xffffu, v, o);
        if (tid == 0) s_inv = 1.0f / v;
    }
    __syncthreads();
    // all DSMEM reads of peer cpart are done -> arrive (wait deferred to kernel end)
    asm volatile("barrier.cluster.arrive.aligned;" ::: "memory");

    // ---- Phase 3: pool my 128 channels, 16 warps x 4 ch/pass x 2 passes ----
    {
        const int warp = tid >> 5;     // 0..15
        const int lane = tid & 31;
        const float inv = s_inv;
        const float4* av = reinterpret_cast<const float4*>(sc);
        #pragma unroll
        for (int blk = 0; blk < CPCTA / (16 * CPW); ++blk) {   // 2 passes
            const int c0 = blk * 16 * CPW + warp * CPW;        // local channel
            const float4* lv = lb4 + (size_t)c0 * CSTR4;
            float acc[CPW] = {0.f, 0.f, 0.f, 0.f};
            for (int i = lane; i < NV4; i += 32) {
                float4 a4 = av[i];
                #pragma unroll
                for (int k = 0; k < CPW; ++k) {
                    float4 l4 = lv[(size_t)k * CSTR4 + i];
                    acc[k] += a4.x * l4.x + a4.y * l4.y + a4.z * l4.z + a4.w * l4.w;
                }
            }
            #pragma unroll
            for (int k = 0; k < CPW; ++k) {
                float a = acc[k];
                #pragma unroll
                for (int o = 16; o; o >>= 1) a += __shfl_xor_sync(0xffffffffu, a, o);
                if (lane == 0)
                    outg[((size_t)n * BC + cbase + c0 + k) * BNF + f] = a * inv;
            }
        }
    }

    // don't exit while peer may still be reading my cpart
    asm volatile("barrier.cluster.wait.aligned;" ::: "memory");
}

extern "C" void kernel_launch(void* const* d_in, const int* in_sizes, int n_in,
                              void* d_out, int out_size)
{
    const float* l = (const float*)d_in[0];
    const float* g = (const float*)d_in[1];
    const float* w = (const float*)d_in[2];
    float* out  = (float*)d_out;
    float* outc = out;                              // 8*16*28*28 = 100352 floats
    float* outg = out + (size_t)BN * BNF * BWH;     // 8*256*16   = 32768 floats

    mfla_kernel<<<BN * BNF * 2, NTHR>>>(l, g, w, outc, outg);
}

// round 9
// speedup vs baseline: 1.0976x; 1.0107x over previous
#include <cuda_runtime.h>
#include <math_constants.h>

#define BN    8
#define BC    256
#define BNF   16
#define BWH   784            // 28*28
#define CSTR  (BNF*BWH)      // 12544 floats between channels
#define CSTR4 (CSTR/4)       // 3136 float4
#define NV4   (BWH/4)        // 196 float4 per wh-row
#define NCHUNK 8             // wh-chunks (K1) / channel-chunks (K2) per tile
#define K1THR 256
#define K2THR 256

// ---------------- K1: c[n,f,wh] = sum_c (l+g)·w  over a wh-chunk ----------------
// 8 warps = 8 channel-groups of 32; lanes = wh4-slots within the chunk.
// Chunk geometry is line-aligned per f-parity:
//   even f: j<7 -> (24j, 24), j=7 -> (168, 28)
//   odd  f: j=0 -> (0, 28),   j>0 -> (24j+4, 24)
__global__ __launch_bounds__(K1THR)
void mfla_c_kernel(const float* __restrict__ l,
                   const float* __restrict__ g,
                   const float* __restrict__ w,
                   float* __restrict__ outc)
{
    __shared__ float sw[BC];
    __shared__ __align__(16) float4 part[8][28];
    __shared__ float red[8];
    __shared__ float s_gdot;

    const int tid  = threadIdx.x;
    const int tile = blockIdx.x >> 3;      // n*16 + f
    const int j    = blockIdx.x & 7;
    const int n    = tile >> 4;
    const int f    = tile & 15;

    int start4, len4;
    if ((f & 1) == 0) { start4 = (j < 7) ? 24 * j : 168; len4 = (j < 7) ? 24 : 28; }
    else              { start4 = (j == 0) ? 0 : 24 * j + 4; len4 = (j == 0) ? 28 : 24; }

    const float4* lb4 = reinterpret_cast<const float4*>(
        l + ((size_t)n * BC * BNF + f) * BWH);

    // weights to smem + gdot
    float wv = w[tid];
    sw[tid] = wv;
    float p = g[n * BC + tid] * wv;
    #pragma unroll
    for (int o = 16; o; o >>= 1) p += __shfl_xor_sync(0xffffffffu, p, o);
    if ((tid & 31) == 0) red[tid >> 5] = p;
    __syncthreads();
    if (tid < 8) {
        float v = red[tid];
        #pragma unroll
        for (int o = 4; o; o >>= 1) v += __shfl_xor_sync(0xffu, v, o);
        if (tid == 0) s_gdot = v;
    }

    // 8 groups x 32 channels; lane = slot within chunk
    {
        const int gq = tid >> 5;           // 0..7
        const int s  = tid & 31;
        if (s < len4) {
            const float4* lp = lb4 + (size_t)(gq * 32) * CSTR4 + start4 + s;
            float4 a = make_float4(0.f, 0.f, 0.f, 0.f);
            #pragma unroll
            for (int c = 0; c < 32; ++c) {
                float4 v = lp[(size_t)c * CSTR4];
                float  ww = sw[gq * 32 + c];
                a.x = fmaf(v.x, ww, a.x);
                a.y = fmaf(v.y, ww, a.y);
                a.z = fmaf(v.z, ww, a.z);
                a.w = fmaf(v.w, ww, a.w);
            }
            part[gq][s] = a;
        }
    }
    __syncthreads();

    if (tid < len4) {
        const float gd = s_gdot;
        float4 v = make_float4(gd, gd, gd, gd);
        #pragma unroll
        for (int k = 0; k < 8; ++k) {
            float4 q = part[k][tid];
            v.x += q.x; v.y += q.y; v.z += q.z; v.w += q.w;
        }
        reinterpret_cast<float4*>(outc + (size_t)tile * BWH)[start4 + tid] = v;
    }
}

// ---------------- K2: softmax over wh (per tile) + pool 32 channels ----------------
__global__ __launch_bounds__(K2THR)
void mfla_pool_kernel(const float* __restrict__ l,
                      const float* __restrict__ outc,
                      float* __restrict__ outg)
{
    __shared__ __align__(16) float sc[BWH];   // exp values
    __shared__ float red[8];
    __shared__ float s_inv;

    const int tid  = threadIdx.x;
    const int tile = blockIdx.x >> 3;      // n*16 + f
    const int cc   = blockIdx.x & 7;       // channel chunk: channels [32cc, 32cc+32)
    const int n    = tile >> 4;
    const int f    = tile & 15;

    // exp + partial sum (196 float4 over 256 threads)
    float se = 0.f;
    if (tid < NV4) {
        float4 c4 = reinterpret_cast<const float4*>(outc + (size_t)tile * BWH)[tid];
        float4 e4 = make_float4(__expf(c4.x), __expf(c4.y), __expf(c4.z), __expf(c4.w));
        reinterpret_cast<float4*>(sc)[tid] = e4;
        se = (e4.x + e4.y) + (e4.z + e4.w);
    }
    #pragma unroll
    for (int o = 16; o; o >>= 1) se += __shfl_xor_sync(0xffffffffu, se, o);
    if ((tid & 31) == 0) red[tid >> 5] = se;
    __syncthreads();
    if (tid < 8) {
        float v = red[tid];
        #pragma unroll
        for (int o = 4; o; o >>= 1) v += __shfl_xor_sync(0xffu, v, o);
        if (tid == 0) s_inv = 1.0f / v;
    }
    __syncthreads();

    // pool: 8 warps x 4 channels each
    {
        const int warp = tid >> 5;          // 0..7
        const int lane = tid & 31;
        const int c0   = 32 * cc + 4 * warp;     // global channel base (4 channels)
        const float inv = s_inv;
        const float4* av = reinterpret_cast<const float4*>(sc);
        const float4* lv = reinterpret_cast<const float4*>(
            l + ((size_t)(n * BC + c0) * BNF + f) * BWH);
        float acc[4] = {0.f, 0.f, 0.f, 0.f};
        for (int i = lane; i < NV4; i += 32) {
            float4 a4 = av[i];
            #pragma unroll
            for (int k = 0; k < 4; ++k) {
                float4 l4 = lv[(size_t)k * CSTR4 + i];
                acc[k] += a4.x * l4.x + a4.y * l4.y + a4.z * l4.z + a4.w * l4.w;
            }
        }
        #pragma unroll
        for (int k = 0; k < 4; ++k) {
            float a = acc[k];
            #pragma unroll
            for (int o = 16; o; o >>= 1) a += __shfl_xor_sync(0xffffffffu, a, o);
            if (lane == 0)
                outg[((size_t)n * BC + c0 + k) * BNF + f] = a * inv;
        }
    }
}

extern "C" void kernel_launch(void* const* d_in, const int* in_sizes, int n_in,
                              void* d_out, int out_size)
{
    const float* l = (const float*)d_in[0];
    const float* g = (const float*)d_in[1];
    const float* w = (const float*)d_in[2];
    float* out  = (float*)d_out;
    float* outc = out;                              // 8*16*28*28 = 100352 floats
    float* outg = out + (size_t)BN * BNF * BWH;     // 8*256*16   = 32768 floats

    mfla_c_kernel   <<<BN * BNF * NCHUNK, K1THR>>>(l, g, w, outc);
    mfla_pool_kernel<<<BN * BNF * NCHUNK, K2THR>>>(l, outc, outg);
}